// round 1
// baseline (speedup 1.0000x reference)
#include <cuda_runtime.h>
#include <math.h>

#define BB 64
#define TT 500
#define SS 50
#define DD 64

// ---- scratch (static device allocations: allowed) ----
__device__ float g_w[(size_t)BB*TT*SS];   // attention weights
__device__ float g_e[(size_t)BB*TT*DD];   // erase gate
__device__ float g_a[(size_t)BB*TT*DD];   // add vector
__device__ float g_r[(size_t)BB*TT*DD];   // read vector

// ============================================================
// Kernel 1a: w = softmax(k @ Mk^T) over s
// grid (10, 64): blockIdx.x = t-tile of 50, blockIdx.y = b. 256 thr.
// ============================================================
__global__ __launch_bounds__(256) void k_scores(const int* __restrict__ concept,
                                                const float* __restrict__ ek,
                                                const float* __restrict__ Mk) {
    int b = blockIdx.y, tile = blockIdx.x;
    int tid = threadIdx.x, g = tid >> 6, d = tid & 63;

    __shared__ float sMkT[DD][SS + 2];           // transposed, padded
    __shared__ __align__(16) float sk[4][DD];
    __shared__ float sexp[4][SS];

    for (int idx = tid; idx < SS * DD; idx += 256) {
        int s = idx / DD, j = idx % DD;
        sMkT[j][s] = Mk[idx];
    }
    __syncthreads();

    int t0 = tile * 50;
    for (int it = 0; it < 13; ++it) {
        int lt = it * 4 + g;
        int t = t0 + lt;
        bool act = lt < 50;
        if (act) {
            int c = concept[b * TT + t];
            sk[g][d] = ek[(size_t)c * DD + d];
        }
        __syncthreads();
        float ex = 0.f;
        if (act && d < SS) {
            float sc = 0.f;
            const float4* k4 = (const float4*)&sk[g][0];
#pragma unroll
            for (int jj = 0; jj < 16; ++jj) {
                float4 kv = k4[jj];
                int j = jj * 4;
                sc += kv.x * sMkT[j][d] + kv.y * sMkT[j + 1][d]
                    + kv.z * sMkT[j + 2][d] + kv.w * sMkT[j + 3][d];
            }
            // scores bounded (|k|~8, |Mk row|~1.7): safe without max-subtraction
            ex = __expf(sc);
            sexp[g][d] = ex;
        }
        __syncthreads();
        if (act && d < SS) {
            float sum = 0.f;
#pragma unroll
            for (int s = 0; s < SS; s++) sum += sexp[g][s];
            g_w[((size_t)(b * TT + t)) * SS + d] = ex / sum;
        }
        __syncthreads();
    }
}

// ============================================================
// Kernel 1b: e = sigmoid(v@We+be), a = tanh(v@Wa+ba)
// ============================================================
__global__ __launch_bounds__(256) void k_ea(const int* __restrict__ concept,
                                            const int* __restrict__ correct,
                                            const int* __restrict__ nc_ptr,
                                            const float* __restrict__ ev,
                                            const float* __restrict__ We,
                                            const float* __restrict__ be,
                                            const float* __restrict__ Wa,
                                            const float* __restrict__ ba) {
    int b = blockIdx.y, tile = blockIdx.x;
    int tid = threadIdx.x, g = tid >> 6, d = tid & 63;
    int nc = *nc_ptr;

    __shared__ float sWe[DD * DD];
    __shared__ float sWa[DD * DD];
    __shared__ float sbe[DD], sba[DD];
    __shared__ __align__(16) float sv[4][DD];

    for (int idx = tid; idx < DD * DD; idx += 256) {
        sWe[idx] = We[idx];
        sWa[idx] = Wa[idx];
    }
    if (tid < DD) { sbe[tid] = be[tid]; sba[tid] = ba[tid]; }
    __syncthreads();

    int t0 = tile * 50;
    for (int it = 0; it < 13; ++it) {
        int lt = it * 4 + g;
        int t = t0 + lt;
        bool act = lt < 50;
        if (act) {
            int c = concept[b * TT + t];
            int x = c + nc * correct[b * TT + t];
            sv[g][d] = ev[(size_t)x * DD + d];
        }
        __syncthreads();
        if (act) {
            float ae = sbe[d], aa = sba[d];
            const float4* v4 = (const float4*)&sv[g][0];
#pragma unroll
            for (int jj = 0; jj < 16; ++jj) {
                float4 v = v4[jj];
                int j = jj * 4;
                ae += v.x * sWe[j * 64 + d];        aa += v.x * sWa[j * 64 + d];
                ae += v.y * sWe[(j + 1) * 64 + d];  aa += v.y * sWa[(j + 1) * 64 + d];
                ae += v.z * sWe[(j + 2) * 64 + d];  aa += v.z * sWa[(j + 2) * 64 + d];
                ae += v.w * sWe[(j + 3) * 64 + d];  aa += v.w * sWa[(j + 3) * 64 + d];
            }
            size_t o = ((size_t)(b * TT + t)) * DD + d;
            g_e[o] = 1.f / (1.f + __expf(-ae));
            g_a[o] = tanhf(aa);
        }
        __syncthreads();
    }
}

// ============================================================
// Kernel 2: sequential scan over t. 128 blocks = (b, d-half).
// 128 threads: d_local = tid>>2 (32 dims), h = tid&3 (s quarter).
// Mv state lives in registers (13 per thread, s padded 50->52 with w=0).
// Double-buffered shared staging of w/e/a to hide global latency.
// ============================================================
__global__ __launch_bounds__(128) void k_scan(const float* __restrict__ Mv0) {
    int blk = blockIdx.x;
    int b = blk >> 1, half = blk & 1;
    int tid = threadIdx.x;
    int dl = tid >> 2, h = tid & 3;
    int d = half * 32 + dl;
    int sbase = h * 13;

    __shared__ float sw[2][56];
    __shared__ float se[2][32], sa[2][32];

    float mv[13];
#pragma unroll
    for (int i = 0; i < 13; i++) {
        int s = sbase + i;
        mv[i] = (s < SS) ? Mv0[s * DD + d] : 0.f;
    }

    // roles: tid<50 -> w ; 64..95 -> e ; 96..127 -> a
    const float* gw = g_w + (size_t)b * TT * SS;
    const float* ge = g_e + (size_t)b * TT * DD + half * 32;
    const float* ga = g_a + (size_t)b * TT * DD + half * 32;
    const float* src = nullptr;
    int stride = 0;
    if (tid < 50)                   { src = gw + tid;        stride = SS; }
    else if (tid >= 64 && tid < 96) { src = ge + (tid - 64); stride = DD; }
    else if (tid >= 96)             { src = ga + (tid - 96); stride = DD; }

    if (tid < 4) sw[tid >> 1][50 + (tid & 1)] = 0.f;  // zero pads, both buffers

    float p = src ? src[0] : 0.f;
    if (tid < 50)                   sw[0][tid] = p;
    else if (tid >= 64 && tid < 96) se[0][tid - 64] = p;
    else if (tid >= 96)             sa[0][tid - 96] = p;
    __syncthreads();

    float* rout = g_r + (size_t)b * TT * DD + d;

    for (int t = 0; t < TT; t++) {
        int cur = t & 1, nxt = cur ^ 1;
        float pn = 0.f;
        if (src && t + 1 < TT) pn = src[(size_t)(t + 1) * stride];   // prefetch

        float e_d = se[cur][dl], a_d = sa[cur][dl];
        float r = 0.f;
#pragma unroll
        for (int i = 0; i < 13; i++) {
            float ws = sw[cur][sbase + i];
            r += ws * mv[i];                          // r uses PRE-update Mv
            mv[i] += ws * fmaf(-mv[i], e_d, a_d);     // Mv += w*(a - Mv*e)
        }
        r += __shfl_xor_sync(0xffffffffu, r, 1);
        r += __shfl_xor_sync(0xffffffffu, r, 2);
        if (h == 0) rout[(size_t)t * DD] = r;

        if (tid < 50)                   sw[nxt][tid] = pn;
        else if (tid >= 64 && tid < 96) se[nxt][tid - 64] = pn;
        else if (tid >= 96)             sa[nxt][tid - 96] = pn;
        __syncthreads();
    }
}

// ============================================================
// Kernel 3: f = tanh([r,k]@Wf+bf); out = sigmoid(3*tanh(f@Wab+bab) - tanh(k@Wd+bd))
// ============================================================
__global__ __launch_bounds__(256) void k_out(const int* __restrict__ concept,
                                             const float* __restrict__ ek,
                                             const float* __restrict__ Wf,
                                             const float* __restrict__ bf,
                                             const float* __restrict__ Wab,
                                             const float* __restrict__ bab,
                                             const float* __restrict__ Wd,
                                             const float* __restrict__ bd,
                                             float* __restrict__ out) {
    int b = blockIdx.y, tile = blockIdx.x;
    int tid = threadIdx.x, g = tid >> 6, d = tid & 63;
    int wg = (tid >> 5) & 1;

    __shared__ float sWf[128 * 64];
    __shared__ float sbf[DD], sWab[DD], sWd[DD];
    __shared__ __align__(16) float srk[4][128];
    __shared__ float sred[4][2][2];

    for (int idx = tid; idx < 128 * 64; idx += 256) sWf[idx] = Wf[idx];
    if (tid < DD) { sbf[tid] = bf[tid]; sWab[tid] = Wab[tid]; sWd[tid] = Wd[tid]; }
    __syncthreads();
    float bab_v = bab[0], bd_v = bd[0];

    int t0 = tile * 50;
    for (int it = 0; it < 13; ++it) {
        int lt = it * 4 + g;
        int t = t0 + lt;
        bool act = lt < 50;
        float kd = 0.f;
        if (act) {
            int c = concept[b * TT + t];
            kd = ek[(size_t)c * DD + d];
            srk[g][d] = g_r[((size_t)(b * TT + t)) * DD + d];
            srk[g][64 + d] = kd;
        }
        __syncthreads();
        if (act) {
            float acc = sbf[d];
            const float4* rk4 = (const float4*)&srk[g][0];
#pragma unroll
            for (int jj = 0; jj < 32; ++jj) {
                float4 v = rk4[jj];
                int j = jj * 4;
                acc += v.x * sWf[j * 64 + d];
                acc += v.y * sWf[(j + 1) * 64 + d];
                acc += v.z * sWf[(j + 2) * 64 + d];
                acc += v.w * sWf[(j + 3) * 64 + d];
            }
            float f = tanhf(acc);
            float pa = f * sWab[d];
            float pq = kd * sWd[d];
#pragma unroll
            for (int o = 16; o > 0; o >>= 1) {
                pa += __shfl_xor_sync(0xffffffffu, pa, o);
                pq += __shfl_xor_sync(0xffffffffu, pq, o);
            }
            if ((tid & 31) == 0) { sred[g][wg][0] = pa; sred[g][wg][1] = pq; }
        }
        __syncthreads();
        if (act && d == 0) {
            float ab = sred[g][0][0] + sred[g][1][0];
            float qd = sred[g][0][1] + sred[g][1][1];
            float val = 3.f * tanhf(ab + bab_v) - tanhf(qd + bd_v);
            out[b * TT + t] = 1.f / (1.f + __expf(-val));
        }
        __syncthreads();
    }
}

// ============================================================
extern "C" void kernel_launch(void* const* d_in, const int* in_sizes, int n_in,
                              void* d_out, int out_size) {
    const int*   concept = (const int*)d_in[0];
    const int*   correct = (const int*)d_in[1];
    const int*   nc      = (const int*)d_in[2];
    const float* ek      = (const float*)d_in[3];
    const float* ev      = (const float*)d_in[4];
    const float* Mk      = (const float*)d_in[5];
    const float* Mv0     = (const float*)d_in[6];
    const float* Wf      = (const float*)d_in[7];
    const float* bf      = (const float*)d_in[8];
    const float* We      = (const float*)d_in[9];
    const float* be      = (const float*)d_in[10];
    const float* Wa      = (const float*)d_in[11];
    const float* ba      = (const float*)d_in[12];
    const float* Wab     = (const float*)d_in[13];
    const float* bab     = (const float*)d_in[14];
    const float* Wd      = (const float*)d_in[15];
    const float* bd      = (const float*)d_in[16];
    float* out = (float*)d_out;

    dim3 gridA(10, 64);
    k_scores<<<gridA, 256>>>(concept, ek, Mk);
    k_ea<<<gridA, 256>>>(concept, correct, nc, ev, We, be, Wa, ba);
    k_scan<<<128, 128>>>(Mv0);
    k_out<<<gridA, 256>>>(concept, ek, Wf, bf, Wab, bab, Wd, bd, out);
}

// round 2
// speedup vs baseline: 1.1897x; 1.1897x over previous
#include <cuda_runtime.h>
#include <math.h>

#define BB 64
#define TT 500
#define SS 50
#define DD 64
#define NTOK (BB*TT)

__device__ float g_w[(size_t)NTOK*SS];
__device__ float g_e[(size_t)NTOK*DD];
__device__ float g_a[(size_t)NTOK*DD];
__device__ float g_r[(size_t)NTOK*DD];

__device__ __forceinline__ float fast_sigmoid(float x) {
    return 1.f / (1.f + __expf(-x));
}
__device__ __forceinline__ float fast_tanh(float x) {
    return fmaf(2.f, fast_sigmoid(2.f * x), -1.f);
}

// ============================================================
// k_scores: w = softmax_s(k @ Mk^T). 32 tokens/block, 1000 blocks.
// thread: td = tid&31 -> s in {td, td+32}; tt = tid>>5 -> tokens {tt+8j}.
// ============================================================
__global__ __launch_bounds__(256) void k_scores(const int* __restrict__ concept,
                                                const float* __restrict__ ek,
                                                const float* __restrict__ Mk) {
    __shared__ __align__(16) float sMk[64 * 68];     // rows 50..63 zero
    __shared__ __align__(16) float sx[32 * 64];
    __shared__ int sc_[32];

    int tid = threadIdx.x;
    int base = blockIdx.x * 32;
    int td = tid & 31, tt = tid >> 5;

    // stage Mk (transpose not needed: contraction over k, rows are s)
    for (int q = tid; q < 64 * 68; q += 256) sMk[q] = 0.f;
    __syncthreads();
    for (int q = tid; q < SS * DD; q += 256) {
        int s = q >> 6, k = q & 63;
        sMk[s * 68 + k] = Mk[q];
    }
    if (tid < 32) sc_[tid] = concept[base + tid];
    __syncthreads();

    // gather k vectors: 512 float4s
    float4* sx4 = (float4*)sx;
    const float4* ek4 = (const float4*)ek;
    for (int q = tid; q < 512; q += 256) {
        int tok = q >> 4, kk = q & 15;
        sx4[q] = ek4[(size_t)sc_[tok] * 16 + kk];
    }
    __syncthreads();

    const float4* sMk4 = (const float4*)sMk;
    float a0[4] = {0,0,0,0}, a1[4] = {0,0,0,0};
#pragma unroll
    for (int kk = 0; kk < 16; ++kk) {
        float4 w0 = sMk4[td * 17 + kk];
        float4 w1 = sMk4[(td + 32) * 17 + kk];
#pragma unroll
        for (int j = 0; j < 4; ++j) {
            float4 xv = sx4[(tt + 8 * j) * 16 + kk];
            a0[j] += xv.x * w0.x + xv.y * w0.y + xv.z * w0.z + xv.w * w0.w;
            a1[j] += xv.x * w1.x + xv.y * w1.y + xv.z * w1.z + xv.w * w1.w;
        }
    }
    bool s1ok = (td + 32) < SS;
#pragma unroll
    for (int j = 0; j < 4; ++j) {
        float e0 = __expf(a0[j]);
        float e1 = s1ok ? __expf(a1[j]) : 0.f;
        float part = e0 + e1;
#pragma unroll
        for (int o = 16; o > 0; o >>= 1)
            part += __shfl_xor_sync(0xffffffffu, part, o);
        float inv = 1.f / part;
        int tok = base + tt + 8 * j;
        g_w[(size_t)tok * SS + td] = e0 * inv;
        if (s1ok) g_w[(size_t)tok * SS + td + 32] = e1 * inv;
    }
}

// ============================================================
// k_ea: e = sigmoid(v@We+be), a = tanh(v@Wa+ba). 32 tokens/block.
// ============================================================
__global__ __launch_bounds__(256) void k_ea(const int* __restrict__ concept,
                                            const int* __restrict__ correct,
                                            const int* __restrict__ nc_ptr,
                                            const float* __restrict__ ev,
                                            const float* __restrict__ We,
                                            const float* __restrict__ be,
                                            const float* __restrict__ Wa,
                                            const float* __restrict__ ba) {
    __shared__ __align__(16) float sWe[64 * 68];   // transposed: [d][j]
    __shared__ __align__(16) float sWa[64 * 68];
    __shared__ __align__(16) float sx[32 * 64];
    __shared__ float sbe[64], sba[64];
    __shared__ int sidx[32];

    int tid = threadIdx.x;
    int base = blockIdx.x * 32;
    int td = tid & 31, tt = tid >> 5;
    int nc = *nc_ptr;

    for (int q = tid; q < 64 * 64; q += 256) {
        int j = q >> 6, d = q & 63;
        sWe[d * 68 + j] = We[q];
        sWa[d * 68 + j] = Wa[q];
    }
    if (tid < 64) { sbe[tid] = be[tid]; sba[tid] = ba[tid]; }
    if (tid < 32) sidx[tid] = concept[base + tid] + nc * correct[base + tid];
    __syncthreads();

    float4* sx4 = (float4*)sx;
    const float4* ev4 = (const float4*)ev;
    for (int q = tid; q < 512; q += 256) {
        int tok = q >> 4, kk = q & 15;
        sx4[q] = ev4[(size_t)sidx[tok] * 16 + kk];
    }
    __syncthreads();

    const float4* sWe4 = (const float4*)sWe;
    const float4* sWa4 = (const float4*)sWa;
    float ae0[4] = {0,0,0,0}, ae1[4] = {0,0,0,0};
    float aa0[4] = {0,0,0,0}, aa1[4] = {0,0,0,0};
#pragma unroll
    for (int kk = 0; kk < 16; ++kk) {
        float4 we0 = sWe4[td * 17 + kk];
        float4 we1 = sWe4[(td + 32) * 17 + kk];
        float4 wa0 = sWa4[td * 17 + kk];
        float4 wa1 = sWa4[(td + 32) * 17 + kk];
#pragma unroll
        for (int j = 0; j < 4; ++j) {
            float4 xv = sx4[(tt + 8 * j) * 16 + kk];
            ae0[j] += xv.x * we0.x + xv.y * we0.y + xv.z * we0.z + xv.w * we0.w;
            ae1[j] += xv.x * we1.x + xv.y * we1.y + xv.z * we1.z + xv.w * we1.w;
            aa0[j] += xv.x * wa0.x + xv.y * wa0.y + xv.z * wa0.z + xv.w * wa0.w;
            aa1[j] += xv.x * wa1.x + xv.y * wa1.y + xv.z * wa1.z + xv.w * wa1.w;
        }
    }
#pragma unroll
    for (int j = 0; j < 4; ++j) {
        size_t tok = (size_t)(base + tt + 8 * j);
        g_e[tok * DD + td]      = fast_sigmoid(ae0[j] + sbe[td]);
        g_e[tok * DD + td + 32] = fast_sigmoid(ae1[j] + sbe[td + 32]);
        g_a[tok * DD + td]      = fast_tanh(aa0[j] + sba[td]);
        g_a[tok * DD + td + 32] = fast_tanh(aa1[j] + sba[td + 32]);
    }
}

// ============================================================
// k_scan: 256 blocks = (b, d-quarter). 128 threads:
// dl = tid>>3 (16 dims), h = tid&7 (8 groups x 7 s-states, pad 50->56).
// Mv in registers, double-buffered staging of w/e/a.
// ============================================================
__global__ __launch_bounds__(128) void k_scan(const float* __restrict__ Mv0) {
    int blk = blockIdx.x;
    int b = blk >> 2, dq = blk & 3;
    int tid = threadIdx.x;
    int dl = tid >> 3, h = tid & 7;
    int d = dq * 16 + dl;
    int sbase = h * 7;

    __shared__ float sw[2][56];
    __shared__ float se[2][16], sa[2][16];

    float mv[7];
#pragma unroll
    for (int i = 0; i < 7; i++) {
        int s = sbase + i;
        mv[i] = (s < SS) ? Mv0[s * DD + d] : 0.f;
    }

    const float* src = nullptr;
    int stride = 0;
    if (tid < 50) { src = g_w + (size_t)b * TT * SS + tid; stride = SS; }
    else if (tid >= 64 && tid < 80) { src = g_e + (size_t)b * TT * DD + dq * 16 + (tid - 64); stride = DD; }
    else if (tid >= 96 && tid < 112) { src = g_a + (size_t)b * TT * DD + dq * 16 + (tid - 96); stride = DD; }

    if (tid >= 50 && tid < 56) { sw[0][tid] = 0.f; sw[1][tid] = 0.f; }

    float p = src ? src[0] : 0.f;
    if (tid < 50) sw[0][tid] = p;
    else if (tid >= 64 && tid < 80) se[0][tid - 64] = p;
    else if (tid >= 96 && tid < 112) sa[0][tid - 96] = p;
    __syncthreads();

    float* rout = g_r + (size_t)b * TT * DD + d;

    for (int t = 0; t < TT; t++) {
        int cur = t & 1, nxt = cur ^ 1;
        float pn = 0.f;
        if (src && t + 1 < TT) pn = src[(size_t)(t + 1) * stride];

        float e_d = se[cur][dl], a_d = sa[cur][dl];
        float r0 = 0.f, r1 = 0.f;
#pragma unroll
        for (int i = 0; i < 7; i++) {
            float ws = sw[cur][sbase + i];
            if (i & 1) r1 += ws * mv[i]; else r0 += ws * mv[i];
            mv[i] = fmaf(ws, fmaf(-mv[i], e_d, a_d), mv[i]);
        }
        float r = r0 + r1;
        r += __shfl_xor_sync(0xffffffffu, r, 1);
        r += __shfl_xor_sync(0xffffffffu, r, 2);
        r += __shfl_xor_sync(0xffffffffu, r, 4);
        if (h == 0) rout[(size_t)t * DD] = r;

        if (tid < 50) sw[nxt][tid] = pn;
        else if (tid >= 64 && tid < 80) se[nxt][tid - 64] = pn;
        else if (tid >= 96 && tid < 112) sa[nxt][tid - 96] = pn;
        __syncthreads();
    }
}

// ============================================================
// k_out: f = tanh([r,k]@Wf+bf); out = sigmoid(3*tanh(f@Wab+bab)-tanh(k@Wd+bd))
// 24 tokens/block, 1334 blocks. thread: td=tid&31 (d, d+32), tt=tid>>5,
// tokens {tt+8j}, j=0..2.
// ============================================================
__global__ __launch_bounds__(256) void k_out(const int* __restrict__ concept,
                                             const float* __restrict__ ek,
                                             const float* __restrict__ Wf,
                                             const float* __restrict__ bf,
                                             const float* __restrict__ Wab,
                                             const float* __restrict__ bab,
                                             const float* __restrict__ Wd,
                                             const float* __restrict__ bd,
                                             float* __restrict__ out) {
    __shared__ __align__(16) float sWf[64 * 132];   // transposed [d][j], j=0..127
    __shared__ __align__(16) float sx[24 * 128];    // [r | k] per token
    __shared__ float sbf[64], sWab[64], sWd[64];
    __shared__ int sc_[24];

    int tid = threadIdx.x;
    int base = blockIdx.x * 24;
    int td = tid & 31, tt = tid >> 5;

    for (int q = tid; q < 128 * 64; q += 256) {
        int j = q >> 6, d = q & 63;
        sWf[d * 132 + j] = Wf[q];
    }
    if (tid < 64) { sbf[tid] = bf[tid]; sWab[tid] = Wab[tid]; sWd[tid] = Wd[tid]; }
    if (tid < 24 && base + tid < NTOK) sc_[tid] = concept[base + tid];
    __syncthreads();

    float4* sx4 = (float4*)sx;
    const float4* gr4 = (const float4*)g_r;
    const float4* ek4 = (const float4*)ek;
    // r part: 24*16 = 384 f4 ; k part: 384 f4
    for (int q = tid; q < 384; q += 256) {
        int tok = q >> 4, kk = q & 15;
        float4 v = make_float4(0,0,0,0);
        if (base + tok < NTOK) v = gr4[(size_t)(base + tok) * 16 + kk];
        sx4[tok * 32 + kk] = v;
    }
    for (int q = tid; q < 384; q += 256) {
        int tok = q >> 4, kk = q & 15;
        float4 v = make_float4(0,0,0,0);
        if (base + tok < NTOK) v = ek4[(size_t)sc_[tok] * 16 + kk];
        sx4[tok * 32 + 16 + kk] = v;
    }
    __syncthreads();

    const float4* sWf4 = (const float4*)sWf;
    float a0[3] = {0,0,0}, a1[3] = {0,0,0};
#pragma unroll
    for (int kk = 0; kk < 32; ++kk) {
        float4 w0 = sWf4[td * 33 + kk];
        float4 w1 = sWf4[(td + 32) * 33 + kk];
#pragma unroll
        for (int j = 0; j < 3; ++j) {
            float4 xv = sx4[(tt + 8 * j) * 32 + kk];
            a0[j] += xv.x * w0.x + xv.y * w0.y + xv.z * w0.z + xv.w * w0.w;
            a1[j] += xv.x * w1.x + xv.y * w1.y + xv.z * w1.z + xv.w * w1.w;
        }
    }
    float bab_v = bab[0], bd_v = bd[0];
#pragma unroll
    for (int j = 0; j < 3; ++j) {
        int tok = tt + 8 * j;
        float f0 = fast_tanh(a0[j] + sbf[td]);
        float f1 = fast_tanh(a1[j] + sbf[td + 32]);
        float pa = f0 * sWab[td] + f1 * sWab[td + 32];
        float kd0 = sx[tok * 128 + 64 + td];
        float kd1 = sx[tok * 128 + 64 + td + 32];
        float pq = kd0 * sWd[td] + kd1 * sWd[td + 32];
#pragma unroll
        for (int o = 16; o > 0; o >>= 1) {
            pa += __shfl_xor_sync(0xffffffffu, pa, o);
            pq += __shfl_xor_sync(0xffffffffu, pq, o);
        }
        if (td == 0 && base + tok < NTOK) {
            float val = 3.f * fast_tanh(pa + bab_v) - fast_tanh(pq + bd_v);
            out[base + tok] = fast_sigmoid(val);
        }
    }
}

// ============================================================
extern "C" void kernel_launch(void* const* d_in, const int* in_sizes, int n_in,
                              void* d_out, int out_size) {
    const int*   concept = (const int*)d_in[0];
    const int*   correct = (const int*)d_in[1];
    const int*   nc      = (const int*)d_in[2];
    const float* ek      = (const float*)d_in[3];
    const float* ev      = (const float*)d_in[4];
    const float* Mk      = (const float*)d_in[5];
    const float* Mv0     = (const float*)d_in[6];
    const float* Wf      = (const float*)d_in[7];
    const float* bf      = (const float*)d_in[8];
    const float* We      = (const float*)d_in[9];
    const float* be      = (const float*)d_in[10];
    const float* Wa      = (const float*)d_in[11];
    const float* ba      = (const float*)d_in[12];
    const float* Wab     = (const float*)d_in[13];
    const float* bab     = (const float*)d_in[14];
    const float* Wd      = (const float*)d_in[15];
    const float* bd      = (const float*)d_in[16];
    float* out = (float*)d_out;

    k_scores<<<1000, 256>>>(concept, ek, Mk);
    k_ea<<<1000, 256>>>(concept, correct, nc, ev, We, be, Wa, ba);
    k_scan<<<256, 128>>>(Mv0);
    k_out<<<(NTOK + 23) / 24, 256>>>(concept, ek, Wf, bf, Wab, bab, Wd, bd, out);
}

// round 3
// speedup vs baseline: 2.3081x; 1.9400x over previous
#include <cuda_runtime.h>
#include <math.h>

#define BB 64
#define TT 500
#define SS 50
#define DD 64
#define NTOK (BB*TT)

__device__ float g_w[(size_t)NTOK*SS];
__device__ float g_e[(size_t)NTOK*DD];
__device__ float g_a[(size_t)NTOK*DD];
__device__ float g_r[(size_t)NTOK*DD];

__device__ __forceinline__ float fast_sigmoid(float x) {
    return 1.f / (1.f + __expf(-x));
}
__device__ __forceinline__ float fast_tanh(float x) {
    return fmaf(2.f, fast_sigmoid(2.f * x), -1.f);
}

// ============================================================
// k_scores: w = softmax_s(k @ Mk^T). 32 tok/block, 128 thr, grid 1000.
// td = tid&15 -> s = 4*td..4*td+3 (contig). tt = tid>>4 -> tok tt+8j.
// Mk transposed in smem: sMkT[k][s], row stride 52.
// ============================================================
#define SROW 52
__global__ __launch_bounds__(128) void k_scores(const int* __restrict__ concept,
                                                const float* __restrict__ ek,
                                                const float* __restrict__ Mk) {
    __shared__ __align__(16) float sMkT[64 * SROW + 16];
    __shared__ __align__(16) float sx[32 * 64];
    __shared__ int sc_[32];

    int tid = threadIdx.x;
    int base = blockIdx.x * 32;
    int td = tid & 15, tt = tid >> 4;

    for (int q = tid; q < 64 * SROW + 16; q += 128) sMkT[q] = 0.f;
    if (tid < 32) sc_[tid] = concept[base + tid];
    __syncthreads();
    for (int q = tid; q < SS * DD; q += 128) {
        int s = q >> 6, k = q & 63;
        sMkT[k * SROW + s] = Mk[q];
    }
    __syncthreads();

    float4* sx4 = (float4*)sx;
    const float4* ek4 = (const float4*)ek;
    for (int q = tid; q < 512; q += 128) {
        int tok = q >> 4, kk = q & 15;
        sx4[q] = ek4[(size_t)sc_[tok] * 16 + kk];
    }
    __syncthreads();

    const float4* sM4 = (const float4*)sMkT;   // row stride 13 f4
    float acc[4][4];
#pragma unroll
    for (int j = 0; j < 4; ++j)
#pragma unroll
        for (int ss = 0; ss < 4; ++ss) acc[j][ss] = 0.f;

#pragma unroll
    for (int kk = 0; kk < 16; ++kk) {
        float4 w0 = sM4[(4 * kk + 0) * 13 + td];
        float4 w1 = sM4[(4 * kk + 1) * 13 + td];
        float4 w2 = sM4[(4 * kk + 2) * 13 + td];
        float4 w3 = sM4[(4 * kk + 3) * 13 + td];
#pragma unroll
        for (int j = 0; j < 4; ++j) {
            float4 xv = sx4[(tt + 8 * j) * 16 + kk];
            acc[j][0] += xv.x * w0.x + xv.y * w1.x + xv.z * w2.x + xv.w * w3.x;
            acc[j][1] += xv.x * w0.y + xv.y * w1.y + xv.z * w2.y + xv.w * w3.y;
            acc[j][2] += xv.x * w0.z + xv.y * w1.z + xv.z * w2.z + xv.w * w3.z;
            acc[j][3] += xv.x * w0.w + xv.y * w1.w + xv.z * w2.w + xv.w * w3.w;
        }
    }

#pragma unroll
    for (int j = 0; j < 4; ++j) {
        float p = 0.f;
#pragma unroll
        for (int ss = 0; ss < 4; ++ss) {
            bool ok = (4 * td + ss) < SS;
            float e = ok ? __expf(acc[j][ss]) : 0.f;
            acc[j][ss] = e;
            p += e;
        }
        p += __shfl_xor_sync(0xffffffffu, p, 1);
        p += __shfl_xor_sync(0xffffffffu, p, 2);
        p += __shfl_xor_sync(0xffffffffu, p, 4);
        p += __shfl_xor_sync(0xffffffffu, p, 8);
        float inv = 1.f / p;
        int tok = base + tt + 8 * j;
        float* gwp = g_w + (size_t)tok * SS + 4 * td;
        if (td < 12) {
            *(float2*)gwp       = make_float2(acc[j][0] * inv, acc[j][1] * inv);
            *(float2*)(gwp + 2) = make_float2(acc[j][2] * inv, acc[j][3] * inv);
        } else if (td == 12) {
            *(float2*)gwp       = make_float2(acc[j][0] * inv, acc[j][1] * inv);
        }
    }
}

// ============================================================
// k_ea: e = sigmoid(v@We+be), a = tanh(v@Wa+ba). 32 tok/block, 128 thr.
// Natural weight layout [j][d]; thread owns d = 4*td..4*td+3.
// ============================================================
__global__ __launch_bounds__(128) void k_ea(const int* __restrict__ concept,
                                            const int* __restrict__ correct,
                                            const int* __restrict__ nc_ptr,
                                            const float* __restrict__ ev,
                                            const float* __restrict__ We,
                                            const float* __restrict__ be,
                                            const float* __restrict__ Wa,
                                            const float* __restrict__ ba) {
    __shared__ __align__(16) float sWe[64 * 64];
    __shared__ __align__(16) float sWa[64 * 64];
    __shared__ __align__(16) float sx[32 * 64];
    __shared__ int sidx[32];

    int tid = threadIdx.x;
    int base = blockIdx.x * 32;
    int td = tid & 15, tt = tid >> 4;
    int nc = *nc_ptr;

    float4* sWe4w = (float4*)sWe;
    float4* sWa4w = (float4*)sWa;
    const float4* We4 = (const float4*)We;
    const float4* Wa4 = (const float4*)Wa;
    for (int q = tid; q < 1024; q += 128) {
        sWe4w[q] = We4[q];
        sWa4w[q] = Wa4[q];
    }
    if (tid < 32) sidx[tid] = concept[base + tid] + nc * correct[base + tid];
    __syncthreads();

    float4* sx4 = (float4*)sx;
    const float4* ev4 = (const float4*)ev;
    for (int q = tid; q < 512; q += 128) {
        int tok = q >> 4, kk = q & 15;
        sx4[q] = ev4[(size_t)sidx[tok] * 16 + kk];
    }
    __syncthreads();

    const float4* sWe4 = (const float4*)sWe;
    const float4* sWa4 = (const float4*)sWa;
    float ae[4][4], aa[4][4];
#pragma unroll
    for (int j = 0; j < 4; ++j)
#pragma unroll
        for (int dd = 0; dd < 4; ++dd) { ae[j][dd] = 0.f; aa[j][dd] = 0.f; }

#pragma unroll
    for (int kk = 0; kk < 16; ++kk) {
        float4 e0 = sWe4[(4 * kk + 0) * 16 + td];
        float4 e1 = sWe4[(4 * kk + 1) * 16 + td];
        float4 e2 = sWe4[(4 * kk + 2) * 16 + td];
        float4 e3 = sWe4[(4 * kk + 3) * 16 + td];
        float4 a0 = sWa4[(4 * kk + 0) * 16 + td];
        float4 a1 = sWa4[(4 * kk + 1) * 16 + td];
        float4 a2 = sWa4[(4 * kk + 2) * 16 + td];
        float4 a3 = sWa4[(4 * kk + 3) * 16 + td];
#pragma unroll
        for (int j = 0; j < 4; ++j) {
            float4 xv = sx4[(tt + 8 * j) * 16 + kk];
            ae[j][0] += xv.x * e0.x + xv.y * e1.x + xv.z * e2.x + xv.w * e3.x;
            ae[j][1] += xv.x * e0.y + xv.y * e1.y + xv.z * e2.y + xv.w * e3.y;
            ae[j][2] += xv.x * e0.z + xv.y * e1.z + xv.z * e2.z + xv.w * e3.z;
            ae[j][3] += xv.x * e0.w + xv.y * e1.w + xv.z * e2.w + xv.w * e3.w;
            aa[j][0] += xv.x * a0.x + xv.y * a1.x + xv.z * a2.x + xv.w * a3.x;
            aa[j][1] += xv.x * a0.y + xv.y * a1.y + xv.z * a2.y + xv.w * a3.y;
            aa[j][2] += xv.x * a0.z + xv.y * a1.z + xv.z * a2.z + xv.w * a3.z;
            aa[j][3] += xv.x * a0.w + xv.y * a1.w + xv.z * a2.w + xv.w * a3.w;
        }
    }

    float4 bev = *(const float4*)(be + 4 * td);
    float4 bav = *(const float4*)(ba + 4 * td);
#pragma unroll
    for (int j = 0; j < 4; ++j) {
        size_t tok = (size_t)(base + tt + 8 * j);
        float4 eo, ao;
        eo.x = fast_sigmoid(ae[j][0] + bev.x);
        eo.y = fast_sigmoid(ae[j][1] + bev.y);
        eo.z = fast_sigmoid(ae[j][2] + bev.z);
        eo.w = fast_sigmoid(ae[j][3] + bev.w);
        ao.x = fast_tanh(aa[j][0] + bav.x);
        ao.y = fast_tanh(aa[j][1] + bav.y);
        ao.z = fast_tanh(aa[j][2] + bav.z);
        ao.w = fast_tanh(aa[j][3] + bav.w);
        *(float4*)(g_e + tok * DD + 4 * td) = eo;
        *(float4*)(g_a + tok * DD + 4 * td) = ao;
    }
}

// ============================================================
// k_scan: 256 blocks = (b, d-quarter). 128 thr: dl=tid>>3, h=tid&7.
// Chunked staging: 10 timesteps per chunk, double-buffered; 2 bars/chunk.
// ============================================================
#define CH 10
__global__ __launch_bounds__(128) void k_scan(const float* __restrict__ Mv0) {
    int b = blockIdx.x >> 2, dq = blockIdx.x & 3;
    int tid = threadIdx.x;
    int dl = tid >> 3, h = tid & 7;
    int d = dq * 16 + dl;
    int sbase = h * 7;

    __shared__ __align__(16) float sw[2][CH][56];
    __shared__ __align__(16) float se[2][CH][16];
    __shared__ __align__(16) float sa[2][CH][16];
    __shared__ __align__(16) float srb[CH][16];

    for (int q = tid; q < 2 * CH * 6; q += 128) {
        int bf = q / (CH * 6), rem = q % (CH * 6), t = rem / 6, p = rem % 6;
        sw[bf][t][50 + p] = 0.f;
    }

    float mv[7];
#pragma unroll
    for (int i = 0; i < 7; i++) {
        int s = sbase + i;
        mv[i] = (s < SS) ? Mv0[s * DD + d] : 0.f;
    }

    const float* gw = g_w + (size_t)b * TT * SS;
    const float* ge = g_e + (size_t)b * TT * DD + dq * 16;
    const float* ga = g_a + (size_t)b * TT * DD + dq * 16;
    float* gr = g_r + (size_t)b * TT * DD + dq * 16;

    float2 wreg[2];
    float4 eareg;

    // load chunk 0
#pragma unroll
    for (int n = 0; n < 2; n++) {
        int q = tid + 128 * n;
        if (q < CH * 25) { int t = q / 25, p = q % 25; wreg[n] = *(const float2*)(gw + (size_t)t * SS + 2 * p); }
    }
    if (tid < 40)      { int t = tid / 4, p = tid % 4; eareg = *(const float4*)(ge + (size_t)t * DD + 4 * p); }
    else if (tid < 80) { int q = tid - 40; int t = q / 4, p = q % 4; eareg = *(const float4*)(ga + (size_t)t * DD + 4 * p); }

#pragma unroll
    for (int n = 0; n < 2; n++) {
        int q = tid + 128 * n;
        if (q < CH * 25) { int t = q / 25, p = q % 25; *(float2*)&sw[0][t][2 * p] = wreg[n]; }
    }
    if (tid < 40)      { int t = tid / 4, p = tid % 4; *(float4*)&se[0][t][4 * p] = eareg; }
    else if (tid < 80) { int q = tid - 40; int t = q / 4, p = q % 4; *(float4*)&sa[0][t][4 * p] = eareg; }
    __syncthreads();

    for (int c = 0; c < TT / CH; ++c) {
        int cur = c & 1;
        if (c < TT / CH - 1) {
            int t0 = (c + 1) * CH;
#pragma unroll
            for (int n = 0; n < 2; n++) {
                int q = tid + 128 * n;
                if (q < CH * 25) { int t = q / 25, p = q % 25; wreg[n] = *(const float2*)(gw + (size_t)(t0 + t) * SS + 2 * p); }
            }
            if (tid < 40)      { int t = tid / 4, p = tid % 4; eareg = *(const float4*)(ge + (size_t)(t0 + t) * DD + 4 * p); }
            else if (tid < 80) { int q = tid - 40; int t = q / 4, p = q % 4; eareg = *(const float4*)(ga + (size_t)(t0 + t) * DD + 4 * p); }
        }

#pragma unroll
        for (int tl = 0; tl < CH; ++tl) {
            float e_d = se[cur][tl][dl], a_d = sa[cur][tl][dl];
            float r = 0.f;
#pragma unroll
            for (int i = 0; i < 7; i++) {
                float ws = sw[cur][tl][sbase + i];
                r += ws * mv[i];
                mv[i] = fmaf(ws, fmaf(-mv[i], e_d, a_d), mv[i]);
            }
            r += __shfl_xor_sync(0xffffffffu, r, 1);
            r += __shfl_xor_sync(0xffffffffu, r, 2);
            r += __shfl_xor_sync(0xffffffffu, r, 4);
            if (h == 0) srb[tl][dl] = r;
        }
        __syncthreads();

        {
            int t0 = c * CH;
            if (tid < 40) {
                int t = tid / 4, p = tid % 4;
                *(float4*)(gr + (size_t)(t0 + t) * DD + 4 * p) = *(const float4*)&srb[t][4 * p];
            }
        }
        if (c < TT / CH - 1) {
            int nb = cur ^ 1;
#pragma unroll
            for (int n = 0; n < 2; n++) {
                int q = tid + 128 * n;
                if (q < CH * 25) { int t = q / 25, p = q % 25; *(float2*)&sw[nb][t][2 * p] = wreg[n]; }
            }
            if (tid < 40)      { int t = tid / 4, p = tid % 4; *(float4*)&se[nb][t][4 * p] = eareg; }
            else if (tid < 80) { int q = tid - 40; int t = q / 4, p = q % 4; *(float4*)&sa[nb][t][4 * p] = eareg; }
        }
        __syncthreads();
    }
}

// ============================================================
// k_out: f = tanh([r,k]@Wf+bf); out = sigmoid(3*tanh(f@Wab+bab)-tanh(k@Wd+bd))
// 24 tok/block, 128 thr, grid 1334. Natural Wf layout [j(128)][d(64)].
// ============================================================
__global__ __launch_bounds__(128) void k_out(const int* __restrict__ concept,
                                             const float* __restrict__ ek,
                                             const float* __restrict__ Wf,
                                             const float* __restrict__ bf,
                                             const float* __restrict__ Wab,
                                             const float* __restrict__ bab,
                                             const float* __restrict__ Wd,
                                             const float* __restrict__ bd,
                                             float* __restrict__ out) {
    __shared__ __align__(16) float sWf[128 * 64];
    __shared__ __align__(16) float sx[24 * 128];
    __shared__ int sc_[24];

    int tid = threadIdx.x;
    int base = blockIdx.x * 24;
    int td = tid & 15, tt = tid >> 4;

    float4* sWf4w = (float4*)sWf;
    const float4* Wf4 = (const float4*)Wf;
    for (int q = tid; q < 2048; q += 128) sWf4w[q] = Wf4[q];
    if (tid < 24) sc_[tid] = (base + tid < NTOK) ? concept[base + tid] : 0;
    __syncthreads();

    float4* sx4 = (float4*)sx;
    const float4* gr4 = (const float4*)g_r;
    const float4* ek4 = (const float4*)ek;
    for (int q = tid; q < 384; q += 128) {
        int tok = q >> 4, kk = q & 15;
        float4 v = make_float4(0, 0, 0, 0);
        if (base + tok < NTOK) v = gr4[(size_t)(base + tok) * 16 + kk];
        sx4[tok * 32 + kk] = v;
        sx4[tok * 32 + 16 + kk] = ek4[(size_t)sc_[tok] * 16 + kk];
    }
    __syncthreads();

    const float4* sWf4 = (const float4*)sWf;
    float acc[3][4];
#pragma unroll
    for (int j = 0; j < 3; ++j)
#pragma unroll
        for (int dd = 0; dd < 4; ++dd) acc[j][dd] = 0.f;

#pragma unroll
    for (int kk = 0; kk < 32; ++kk) {
        float4 w0 = sWf4[(4 * kk + 0) * 16 + td];
        float4 w1 = sWf4[(4 * kk + 1) * 16 + td];
        float4 w2 = sWf4[(4 * kk + 2) * 16 + td];
        float4 w3 = sWf4[(4 * kk + 3) * 16 + td];
#pragma unroll
        for (int j = 0; j < 3; ++j) {
            float4 xv = sx4[(tt + 8 * j) * 32 + kk];
            acc[j][0] += xv.x * w0.x + xv.y * w1.x + xv.z * w2.x + xv.w * w3.x;
            acc[j][1] += xv.x * w0.y + xv.y * w1.y + xv.z * w2.y + xv.w * w3.y;
            acc[j][2] += xv.x * w0.z + xv.y * w1.z + xv.z * w2.z + xv.w * w3.z;
            acc[j][3] += xv.x * w0.w + xv.y * w1.w + xv.z * w2.w + xv.w * w3.w;
        }
    }

    float4 bfv = *(const float4*)(bf + 4 * td);
    float4 wabv = *(const float4*)(Wab + 4 * td);
    float4 wdv = *(const float4*)(Wd + 4 * td);
    float bab0 = bab[0], bd0 = bd[0];

#pragma unroll
    for (int j = 0; j < 3; ++j) {
        int tok = tt + 8 * j;
        float f0 = fast_tanh(acc[j][0] + bfv.x);
        float f1 = fast_tanh(acc[j][1] + bfv.y);
        float f2 = fast_tanh(acc[j][2] + bfv.z);
        float f3 = fast_tanh(acc[j][3] + bfv.w);
        float pa = f0 * wabv.x + f1 * wabv.y + f2 * wabv.z + f3 * wabv.w;
        float4 kd = *(const float4*)&sx[tok * 128 + 64 + 4 * td];
        float pq = kd.x * wdv.x + kd.y * wdv.y + kd.z * wdv.z + kd.w * wdv.w;
#pragma unroll
        for (int o = 8; o > 0; o >>= 1) {
            pa += __shfl_xor_sync(0xffffffffu, pa, o);
            pq += __shfl_xor_sync(0xffffffffu, pq, o);
        }
        if (td == 0 && base + tok < NTOK) {
            float val = 3.f * fast_tanh(pa + bab0) - fast_tanh(pq + bd0);
            out[base + tok] = fast_sigmoid(val);
        }
    }
}

// ============================================================
extern "C" void kernel_launch(void* const* d_in, const int* in_sizes, int n_in,
                              void* d_out, int out_size) {
    const int*   concept = (const int*)d_in[0];
    const int*   correct = (const int*)d_in[1];
    const int*   nc      = (const int*)d_in[2];
    const float* ek      = (const float*)d_in[3];
    const float* ev      = (const float*)d_in[4];
    const float* Mk      = (const float*)d_in[5];
    const float* Mv0     = (const float*)d_in[6];
    const float* Wf      = (const float*)d_in[7];
    const float* bf      = (const float*)d_in[8];
    const float* We      = (const float*)d_in[9];
    const float* be      = (const float*)d_in[10];
    const float* Wa      = (const float*)d_in[11];
    const float* ba      = (const float*)d_in[12];
    const float* Wab     = (const float*)d_in[13];
    const float* bab     = (const float*)d_in[14];
    const float* Wd      = (const float*)d_in[15];
    const float* bd      = (const float*)d_in[16];
    float* out = (float*)d_out;

    k_scores<<<1000, 128>>>(concept, ek, Mk);
    k_ea<<<1000, 128>>>(concept, correct, nc, ev, We, be, Wa, ba);
    k_scan<<<256, 128>>>(Mv0);
    k_out<<<(NTOK + 23) / 24, 128>>>(concept, ek, Wf, bf, Wab, bab, Wd, bd, out);
}